// round 13
// baseline (speedup 1.0000x reference)
#include <cuda_runtime.h>
#include <cuda_bf16.h>
#include <math.h>
#include <stdint.h>

#define B_DIM 64
#define S_DIM 1000
#define K_DIM 12
#define N_DIM 80
#define NP 81
#define EPS 1e-5f
#define LOG_2PI 1.8378770664093453f
#define SUBT 63                       // ceil(1000/16) m-subtiles

// ---- device scratch (no allocations allowed) ----
__device__ float g_cst[B_DIM * K_DIM];
__device__ float g_c[B_DIM * K_DIM * N_DIM];
// B operand packed as m16n8k16 B-fragment image:
// idx = bk*1600 + ((kc*4+t)*80 + n);  .x = pack(W[kc*16+2t][n], W[kc*16+2t+1][n])
//                                     .y = pack(W[kc*16+2t+8][n], W[kc*16+2t+9][n])
__device__ uint2 g_wqhi[B_DIM * K_DIM * 1600];
__device__ uint2 g_wqlo[B_DIM * K_DIM * 1600];
// A operand packed as m16n8k16 A-fragment image (uint4 = 4 frag regs per lane/kc):
// idx = ((b*SUBT + ms)*5 + kc)*32 + lane
__device__ uint4 g_afhi[B_DIM * SUBT * 5 * 32];
__device__ uint4 g_aflo[B_DIM * SUBT * 5 * 32];

__device__ __forceinline__ uint32_t pack_bf16(__nv_bfloat16 lo, __nv_bfloat16 hi) {
    return (uint32_t)__bfloat16_as_ushort(lo) | ((uint32_t)__bfloat16_as_ushort(hi) << 16);
}
__device__ __forceinline__ uint32_t hi_pack(float a, float b) {
    return pack_bf16(__float2bfloat16(a), __float2bfloat16(b));
}
__device__ __forceinline__ uint32_t lo_pack(float a, float b) {
    __nv_bfloat16 ha = __float2bfloat16(a), hb = __float2bfloat16(b);
    return pack_bf16(__float2bfloat16(a - __bfloat162float(ha)),
                     __float2bfloat16(b - __bfloat162float(hb)));
}

__device__ __forceinline__ void mma16816(float d[4], const uint32_t a[4], uint32_t b0, uint32_t b1) {
    asm volatile(
        "mma.sync.aligned.m16n8k16.row.col.f32.bf16.bf16.f32 "
        "{%0,%1,%2,%3}, {%4,%5,%6,%7}, {%8,%9}, {%0,%1,%2,%3};"
        : "+f"(d[0]), "+f"(d[1]), "+f"(d[2]), "+f"(d[3])
        : "r"(a[0]), "r"(a[1]), "r"(a[2]), "r"(a[3]), "r"(b0), "r"(b1));
}

// ---------------------------------------------------------------------------
// convert_x: build the A-fragment image. One thread per (b, ms, kc, lane).
// ---------------------------------------------------------------------------
__global__ void __launch_bounds__(256) convert_x(const float* __restrict__ x) {
    int idx = blockIdx.x * 256 + threadIdx.x;
    if (idx >= B_DIM * SUBT * 5 * 32) return;
    int lane = idx & 31;
    int rest = idx >> 5;
    int kc = rest % 5;  rest /= 5;
    int ms = rest % SUBT;
    int b  = rest / SUBT;
    int g = lane >> 2, t = lane & 3;
    int sa = ms * 16 + g, sb = sa + 8;
    int w0 = kc * 8 + t, w1 = w0 + 4;
    const float2* xb = (const float2*)(x + (size_t)b * S_DIM * N_DIM);
    float2 z = make_float2(0.f, 0.f);
    float2 a0 = (sa < S_DIM) ? xb[sa * 40 + w0] : z;
    float2 b0 = (sb < S_DIM) ? xb[sb * 40 + w0] : z;
    float2 a1 = (sa < S_DIM) ? xb[sa * 40 + w1] : z;
    float2 b1 = (sb < S_DIM) ? xb[sb * 40 + w1] : z;
    g_afhi[idx] = make_uint4(hi_pack(a0.x, a0.y), hi_pack(b0.x, b0.y),
                             hi_pack(a1.x, a1.y), hi_pack(b1.x, b1.y));
    g_aflo[idx] = make_uint4(lo_pack(a0.x, a0.y), lo_pack(b0.x, b0.y),
                             lo_pack(a1.x, a1.y), lo_pack(b1.x, b1.y));
}

// ---------------------------------------------------------------------------
// Prep per (b,k), 128 threads. Pivot column copied to separate smem (colj)
// each step -> alias-free trailing update that ptxas can pipeline.
// (unchanged from R12 — isolates this round's ll change)
// ---------------------------------------------------------------------------
__global__ void __launch_bounds__(128) prep_kernel(const float* __restrict__ mu,
                                                   const float* __restrict__ sigma) {
    __shared__ float A[N_DIM * NP];     // 25.9 KB
    __shared__ float colj[N_DIM];
    __shared__ float Tb[40 * 41];       // 6.6 KB
    __shared__ float rs[N_DIM];
    __shared__ float lg[N_DIM];

    int bk = blockIdx.x;
    int tid = threadIdx.x;

    const float* sig = sigma + (size_t)bk * N_DIM * N_DIM;
    for (int p = tid; p < N_DIM * N_DIM; p += 128) {
        int i = p / N_DIM, j = p % N_DIM;
        float v = sig[p];
        if (i == j) v += EPS;
        A[i * NP + j] = v;
    }

    // ---- LDL^T (unnormalized): pivot j; thread owns trailing column c
    for (int j = 0; j < N_DIM - 1; j++) {
        __syncthreads();
        for (int r = j + tid; r < N_DIM; r += 128) colj[r] = A[r * NP + j];
        __syncthreads();
        float invj = 1.0f / colj[j];
        int c = j + 1 + tid;
        if (c < N_DIM) {
            float f = invj * colj[c];
            #pragma unroll 4
            for (int r = c; r < N_DIM; r++)
                A[r * NP + c] -= colj[r] * f;
        }
    }
    __syncthreads();

    // ---- diag -> rs, lg
    if (tid < N_DIM) {
        float d = A[tid * NP + tid];
        rs[tid] = rsqrtf(d);
        lg[tid] = 0.5f * logf(d);
    }
    __syncthreads();

    // ---- normalize to Cholesky L
    for (int p = tid; p < N_DIM * N_DIM; p += 128) {
        int i = p / N_DIM, j = p % N_DIM;
        if (i >= j) A[i * NP + j] *= rs[j];
    }
    if (tid == 0) {
        float s = 0.f;
        for (int j = 0; j < N_DIM; j++) s += lg[j];
        g_cst[bk] = -s - 0.5f * N_DIM * LOG_2PI;
    }
    __syncthreads();

    // ---- two independent 40x40 triangular inversions (one column per thread)
    if (tid < N_DIM) {
        int j = tid;
        int hi = (j < 40) ? 40 : 80;
        for (int i = j + 1; i < hi; i++) {
            float s = A[i * NP + j] * rs[j];
            for (int t = j + 1; t < i; t++)
                s += A[i * NP + t] * A[j * NP + t];
            A[j * NP + i] = -s * rs[i];
        }
    }
    __syncthreads();

    // ---- Tb = L10 * M00
    for (int p = tid; p < 1600; p += 128) {
        int ii = p / 40, jj = p % 40;
        float s = A[(40 + ii) * NP + jj] * rs[jj];
        for (int t = jj + 1; t < 40; t++)
            s += A[(40 + ii) * NP + t] * A[jj * NP + t];
        Tb[ii * 41 + jj] = s;
    }
    __syncthreads();

    // ---- M10 = -M11 * Tb
    for (int p = tid; p < 1600; p += 128) {
        int ii = p / 40, jj = p % 40;
        float s = rs[40 + ii] * Tb[ii * 41 + jj];
        for (int t = 0; t < ii; t++)
            s += A[(40 + t) * NP + (40 + ii)] * Tb[t * 41 + jj];
        A[jj * NP + (40 + ii)] = -s;
    }
    __syncthreads();

    // ---- c = M * mu
    const float* mub = mu + (size_t)bk * N_DIM;
    if (tid < N_DIM) {
        int j = tid;
        float c = mub[j] * rs[j];
        for (int i = 0; i < j; i++) c += mub[i] * A[i * NP + j];
        g_c[bk * N_DIM + j] = c;
    }
    __syncthreads();

    // ---- Emit packed B fragments. W[k][n]: k<n -> A[k*NP+n]; k==n -> rs[k]; else 0
    uint2* wh = g_wqhi + (size_t)bk * 1600;
    uint2* wl = g_wqlo + (size_t)bk * 1600;
    for (int p = tid; p < 1600; p += 128) {
        int kc = p / 320;
        int t  = (p / 80) % 4;
        int n  = p % 80;
        int k0 = kc * 16 + 2 * t;
        float w[4];
        #pragma unroll
        for (int q = 0; q < 4; q++) {
            int k = k0 + ((q >= 2) ? 8 : 0) + (q & 1);
            float v = 0.f;
            if (k < n)       v = A[k * NP + n];
            else if (k == n) v = rs[k];
            w[q] = v;
        }
        wh[p] = make_uint2(hi_pack(w[0], w[1]), hi_pack(w[2], w[3]));
        wl[p] = make_uint2(lo_pack(w[0], w[1]), lo_pack(w[2], w[3]));
    }
}

// ---------------------------------------------------------------------------
// Main: CTA = (subtile-group of 8, b), 256 threads. Warp w owns subtile
// grp*8+w and keeps its A fragments (hi/lo, 40 regs) resident across ALL 12
// states. B-fragment images double-buffered in smem: stage state k+1 while
// computing state k; ONE barrier per state. Triangular kc <= jp skip kept.
// ---------------------------------------------------------------------------
#define WQ_STRIDE 84
#define WQ_BUF (2 * 20 * WQ_STRIDE)              // uint2 per buffer (incl hi+lo)
#define SM_TOTAL (2 * WQ_BUF * 8)                // 53760 B

__global__ void __launch_bounds__(256, 2) ll_mma_kernel(float* __restrict__ out) {
    extern __shared__ uint2 WQ[];                // [2][2*20*WQ_STRIDE]

    int tid = threadIdx.x;
    int wid = tid >> 5, lid = tid & 31;
    int g = lid >> 2, t = lid & 3;
    int grp = blockIdx.x, b = blockIdx.y;
    int ms = grp * 8 + wid;
    bool active = (ms < SUBT);

    // ---- resident A fragments (loaded once, reused for all 12 states)
    uint4 AH[5], AL[5];
    if (active) {
        const uint4* ah = g_afhi + ((size_t)(b * SUBT + ms)) * 5 * 32 + lid;
        const uint4* al = g_aflo + ((size_t)(b * SUBT + ms)) * 5 * 32 + lid;
        #pragma unroll
        for (int kc = 0; kc < 5; kc++) {
            AH[kc] = ah[kc * 32];
            AL[kc] = al[kc * 32];
        }
    }

    // ---- stage state 0 into buffer 0
    {
        const uint2* wh = g_wqhi + (size_t)(b * K_DIM) * 1600;
        const uint2* wl = g_wqlo + (size_t)(b * K_DIM) * 1600;
        for (int p = tid; p < 1600; p += 256) {
            int row = p / 80, n = p % 80;
            WQ[row * WQ_STRIDE + n]                  = wh[p];
            WQ[20 * WQ_STRIDE + row * WQ_STRIDE + n] = wl[p];
        }
    }
    __syncthreads();

    int sa = ms * 16 + g, sb = sa + 8;

    for (int k = 0; k < K_DIM; k++) {
        // ---- stage state k+1 into the other buffer (overlaps compute)
        if (k + 1 < K_DIM) {
            int bk1 = b * K_DIM + k + 1;
            uint2* dst = WQ + ((k + 1) & 1) * WQ_BUF;
            const uint2* wh = g_wqhi + (size_t)bk1 * 1600;
            const uint2* wl = g_wqlo + (size_t)bk1 * 1600;
            for (int p = tid; p < 1600; p += 256) {
                int row = p / 80, n = p % 80;
                dst[row * WQ_STRIDE + n]                  = wh[p];
                dst[20 * WQ_STRIDE + row * WQ_STRIDE + n] = wl[p];
            }
        }

        // ---- compute state k from buffer k&1
        if (active) {
            int bk = b * K_DIM + k;
            const uint2* buf = WQ + (k & 1) * WQ_BUF;
            float2 cc[10];
            const float* cbase = g_c + bk * N_DIM;
            #pragma unroll
            for (int j = 0; j < 10; j++)
                cc[j] = *(const float2*)(cbase + j * 8 + 2 * t);
            float cst = g_cst[bk];

            float qa0 = 0.f, qa1 = 0.f, qb0 = 0.f, qb1 = 0.f;
            #pragma unroll
            for (int jp = 0; jp < 5; jp++) {
                float d0[4] = {0.f, 0.f, 0.f, 0.f};
                float d1[4] = {0.f, 0.f, 0.f, 0.f};
                int n0 = jp * 16 + g;
                int n1 = n0 + 8;
                #pragma unroll
                for (int kc = 0; kc <= jp; kc++) {     // triangular: kc <= j/2
                    int row = (kc * 4 + t) * WQ_STRIDE;
                    uint2 bh0 = buf[row + n0];
                    uint2 bh1 = buf[row + n1];
                    uint2 bl0 = buf[20 * WQ_STRIDE + row + n0];
                    uint2 bl1 = buf[20 * WQ_STRIDE + row + n1];
                    const uint32_t* ah32 = (const uint32_t*)&AH[kc];
                    const uint32_t* al32 = (const uint32_t*)&AL[kc];
                    mma16816(d0, ah32, bh0.x, bh0.y);
                    mma16816(d1, ah32, bh1.x, bh1.y);
                    mma16816(d0, al32, bh0.x, bh0.y);
                    mma16816(d1, al32, bh1.x, bh1.y);
                    mma16816(d0, ah32, bl0.x, bl0.y);
                    mma16816(d1, ah32, bl1.x, bl1.y);
                }
                float2 c0 = cc[2 * jp], c1 = cc[2 * jp + 1];
                float e;
                e = d0[0] - c0.x; qa0 = fmaf(e, e, qa0);
                e = d0[1] - c0.y; qa1 = fmaf(e, e, qa1);
                e = d0[2] - c0.x; qb0 = fmaf(e, e, qb0);
                e = d0[3] - c0.y; qb1 = fmaf(e, e, qb1);
                e = d1[0] - c1.x; qa0 = fmaf(e, e, qa0);
                e = d1[1] - c1.y; qa1 = fmaf(e, e, qa1);
                e = d1[2] - c1.x; qb0 = fmaf(e, e, qb0);
                e = d1[3] - c1.y; qb1 = fmaf(e, e, qb1);
            }
            float qa = qa0 + qa1, qb = qb0 + qb1;
            qa += __shfl_xor_sync(0xffffffffu, qa, 1);
            qa += __shfl_xor_sync(0xffffffffu, qa, 2);
            qb += __shfl_xor_sync(0xffffffffu, qb, 1);
            qb += __shfl_xor_sync(0xffffffffu, qb, 2);
            if (t == 0) {
                if (sa < S_DIM)
                    out[((size_t)b * S_DIM + sa) * K_DIM + k] = fmaf(-0.5f, qa, cst);
                if (sb < S_DIM)
                    out[((size_t)b * S_DIM + sb) * K_DIM + k] = fmaf(-0.5f, qb, cst);
            }
        }
        __syncthreads();   // staging k+1 done AND compute k done
    }
}

// ---------------------------------------------------------------------------
extern "C" void kernel_launch(void* const* d_in, const int* in_sizes, int n_in,
                              void* d_out, int out_size) {
    const float* x     = (const float*)d_in[0];
    const float* mu    = (const float*)d_in[1];
    const float* sigma = (const float*)d_in[2];
    float* out = (float*)d_out;

    convert_x<<<(B_DIM * SUBT * 5 * 32 + 255) / 256, 256>>>(x);
    prep_kernel<<<B_DIM * K_DIM, 128>>>(mu, sigma);

    cudaFuncSetAttribute(ll_mma_kernel, cudaFuncAttributeMaxDynamicSharedMemorySize, SM_TOTAL);
    ll_mma_kernel<<<dim3(8, B_DIM), 256, SM_TOTAL>>>(out);
}

// round 14
// speedup vs baseline: 1.1102x; 1.1102x over previous
#include <cuda_runtime.h>
#include <cuda_bf16.h>
#include <math.h>
#include <stdint.h>

#define B_DIM 64
#define S_DIM 1000
#define K_DIM 12
#define N_DIM 80
#define NP 81
#define EPS 1e-5f
#define LOG_2PI 1.8378770664093453f
#define SUBT 63                       // ceil(1000/16) m-subtiles

// ---- device scratch (no allocations allowed) ----
__device__ float g_cst[B_DIM * K_DIM];
__device__ float g_c[B_DIM * K_DIM * N_DIM];
// B operand packed as m16n8k16 B-fragment image:
// idx = bk*1600 + ((kc*4+t)*80 + n);  .x = pack(W[kc*16+2t][n], W[kc*16+2t+1][n])
//                                     .y = pack(W[kc*16+2t+8][n], W[kc*16+2t+9][n])
__device__ uint2 g_wqhi[B_DIM * K_DIM * 1600];
__device__ uint2 g_wqlo[B_DIM * K_DIM * 1600];
// A operand packed as m16n8k16 A-fragment image (uint4 = 4 frag regs per lane/kc):
// idx = ((b*SUBT + ms)*5 + kc)*32 + lane
__device__ uint4 g_afhi[B_DIM * SUBT * 5 * 32];
__device__ uint4 g_aflo[B_DIM * SUBT * 5 * 32];

__device__ __forceinline__ uint32_t pack_bf16(__nv_bfloat16 lo, __nv_bfloat16 hi) {
    return (uint32_t)__bfloat16_as_ushort(lo) | ((uint32_t)__bfloat16_as_ushort(hi) << 16);
}
__device__ __forceinline__ uint32_t hi_pack(float a, float b) {
    return pack_bf16(__float2bfloat16(a), __float2bfloat16(b));
}
__device__ __forceinline__ uint32_t lo_pack(float a, float b) {
    __nv_bfloat16 ha = __float2bfloat16(a), hb = __float2bfloat16(b);
    return pack_bf16(__float2bfloat16(a - __bfloat162float(ha)),
                     __float2bfloat16(b - __bfloat162float(hb)));
}

__device__ __forceinline__ void mma16816(float d[4], const uint32_t a[4], uint32_t b0, uint32_t b1) {
    asm volatile(
        "mma.sync.aligned.m16n8k16.row.col.f32.bf16.bf16.f32 "
        "{%0,%1,%2,%3}, {%4,%5,%6,%7}, {%8,%9}, {%0,%1,%2,%3};"
        : "+f"(d[0]), "+f"(d[1]), "+f"(d[2]), "+f"(d[3])
        : "r"(a[0]), "r"(a[1]), "r"(a[2]), "r"(a[3]), "r"(b0), "r"(b1));
}

// ---------------------------------------------------------------------------
// convert_x: build the A-fragment image. One thread per (b, ms, kc, lane).
// ---------------------------------------------------------------------------
__global__ void __launch_bounds__(256) convert_x(const float* __restrict__ x) {
    int idx = blockIdx.x * 256 + threadIdx.x;
    if (idx >= B_DIM * SUBT * 5 * 32) return;
    int lane = idx & 31;
    int rest = idx >> 5;
    int kc = rest % 5;  rest /= 5;
    int ms = rest % SUBT;
    int b  = rest / SUBT;
    int g = lane >> 2, t = lane & 3;
    int sa = ms * 16 + g, sb = sa + 8;
    int w0 = kc * 8 + t, w1 = w0 + 4;
    const float2* xb = (const float2*)(x + (size_t)b * S_DIM * N_DIM);
    float2 z = make_float2(0.f, 0.f);
    float2 a0 = (sa < S_DIM) ? xb[sa * 40 + w0] : z;
    float2 b0 = (sb < S_DIM) ? xb[sb * 40 + w0] : z;
    float2 a1 = (sa < S_DIM) ? xb[sa * 40 + w1] : z;
    float2 b1 = (sb < S_DIM) ? xb[sb * 40 + w1] : z;
    g_afhi[idx] = make_uint4(hi_pack(a0.x, a0.y), hi_pack(b0.x, b0.y),
                             hi_pack(a1.x, a1.y), hi_pack(b1.x, b1.y));
    g_aflo[idx] = make_uint4(lo_pack(a0.x, a0.y), lo_pack(b0.x, b0.y),
                             lo_pack(a1.x, a1.y), lo_pack(b1.x, b1.y));
}

// ---------------------------------------------------------------------------
// Prep per (b,k), 128 threads. Pivot column copied to separate smem (colj)
// each step -> alias-free trailing update that ptxas can pipeline.
// ---------------------------------------------------------------------------
__global__ void __launch_bounds__(128) prep_kernel(const float* __restrict__ mu,
                                                   const float* __restrict__ sigma) {
    __shared__ float A[N_DIM * NP];     // 25.9 KB
    __shared__ float colj[N_DIM];
    __shared__ float Tb[40 * 41];       // 6.6 KB
    __shared__ float rs[N_DIM];
    __shared__ float lg[N_DIM];

    int bk = blockIdx.x;
    int tid = threadIdx.x;

    const float* sig = sigma + (size_t)bk * N_DIM * N_DIM;
    for (int p = tid; p < N_DIM * N_DIM; p += 128) {
        int i = p / N_DIM, j = p % N_DIM;
        float v = sig[p];
        if (i == j) v += EPS;
        A[i * NP + j] = v;
    }

    // ---- LDL^T (unnormalized): pivot j; thread owns trailing column c
    for (int j = 0; j < N_DIM - 1; j++) {
        __syncthreads();
        for (int r = j + tid; r < N_DIM; r += 128) colj[r] = A[r * NP + j];
        __syncthreads();
        float invj = 1.0f / colj[j];
        int c = j + 1 + tid;
        if (c < N_DIM) {
            float f = invj * colj[c];
            #pragma unroll 4
            for (int r = c; r < N_DIM; r++)
                A[r * NP + c] -= colj[r] * f;
        }
    }
    __syncthreads();

    // ---- diag -> rs, lg
    if (tid < N_DIM) {
        float d = A[tid * NP + tid];
        rs[tid] = rsqrtf(d);
        lg[tid] = 0.5f * logf(d);
    }
    __syncthreads();

    // ---- normalize to Cholesky L
    for (int p = tid; p < N_DIM * N_DIM; p += 128) {
        int i = p / N_DIM, j = p % N_DIM;
        if (i >= j) A[i * NP + j] *= rs[j];
    }
    if (tid == 0) {
        float s = 0.f;
        for (int j = 0; j < N_DIM; j++) s += lg[j];
        g_cst[bk] = -s - 0.5f * N_DIM * LOG_2PI;
    }
    __syncthreads();

    // ---- two independent 40x40 triangular inversions (one column per thread)
    if (tid < N_DIM) {
        int j = tid;
        int hi = (j < 40) ? 40 : 80;
        for (int i = j + 1; i < hi; i++) {
            float s = A[i * NP + j] * rs[j];
            for (int t = j + 1; t < i; t++)
                s += A[i * NP + t] * A[j * NP + t];
            A[j * NP + i] = -s * rs[i];
        }
    }
    __syncthreads();

    // ---- Tb = L10 * M00
    for (int p = tid; p < 1600; p += 128) {
        int ii = p / 40, jj = p % 40;
        float s = A[(40 + ii) * NP + jj] * rs[jj];
        for (int t = jj + 1; t < 40; t++)
            s += A[(40 + ii) * NP + t] * A[jj * NP + t];
        Tb[ii * 41 + jj] = s;
    }
    __syncthreads();

    // ---- M10 = -M11 * Tb
    for (int p = tid; p < 1600; p += 128) {
        int ii = p / 40, jj = p % 40;
        float s = rs[40 + ii] * Tb[ii * 41 + jj];
        for (int t = 0; t < ii; t++)
            s += A[(40 + t) * NP + (40 + ii)] * Tb[t * 41 + jj];
        A[jj * NP + (40 + ii)] = -s;
    }
    __syncthreads();

    // ---- c = M * mu
    const float* mub = mu + (size_t)bk * N_DIM;
    if (tid < N_DIM) {
        int j = tid;
        float c = mub[j] * rs[j];
        for (int i = 0; i < j; i++) c += mub[i] * A[i * NP + j];
        g_c[bk * N_DIM + j] = c;
    }
    __syncthreads();

    // ---- Emit packed B fragments. W[k][n]: k<n -> A[k*NP+n]; k==n -> rs[k]; else 0
    uint2* wh = g_wqhi + (size_t)bk * 1600;
    uint2* wl = g_wqlo + (size_t)bk * 1600;
    for (int p = tid; p < 1600; p += 128) {
        int kc = p / 320;
        int t  = (p / 80) % 4;
        int n  = p % 80;
        int k0 = kc * 16 + 2 * t;
        float w[4];
        #pragma unroll
        for (int q = 0; q < 4; q++) {
            int k = k0 + ((q >= 2) ? 8 : 0) + (q & 1);
            float v = 0.f;
            if (k < n)       v = A[k * NP + n];
            else if (k == n) v = rs[k];
            w[q] = v;
        }
        wh[p] = make_uint2(hi_pack(w[0], w[1]), hi_pack(w[2], w[3]));
        wl[p] = make_uint2(lo_pack(w[0], w[1]), lo_pack(w[2], w[3]));
    }
}

// ---------------------------------------------------------------------------
// Main (R12 version — best known): CTA per (b,k), 256 threads (8 warps).
// B-fragment image staged ONCE; c/cst in registers; ONE __syncthreads.
// Warps sweep 63 m-subtiles stride-8. Triangular skip: kc <= jp.
// ---------------------------------------------------------------------------
#define WQ_STRIDE 84

__global__ void __launch_bounds__(256) ll_mma_kernel(float* __restrict__ out) {
    __shared__ uint2 WQ[2 * 20 * WQ_STRIDE];   // 26880 B

    int tid = threadIdx.x;
    int wid = tid >> 5, lid = tid & 31;
    int g = lid >> 2, t = lid & 3;
    int k = blockIdx.x, b = blockIdx.y;
    int bk = b * K_DIM + k;

    // stage B fragments (once)
    {
        const uint2* wh = g_wqhi + (size_t)bk * 1600;
        const uint2* wl = g_wqlo + (size_t)bk * 1600;
        for (int p = tid; p < 1600; p += 256) {
            int row = p / 80, n = p % 80;
            WQ[row * WQ_STRIDE + n]                  = wh[p];
            WQ[20 * WQ_STRIDE + row * WQ_STRIDE + n] = wl[p];
        }
    }
    // c fragments + cst to registers
    float2 cc[10];
    {
        const float* cbase = g_c + bk * N_DIM;
        #pragma unroll
        for (int j = 0; j < 10; j++)
            cc[j] = *(const float2*)(cbase + j * 8 + 2 * t);
    }
    float cst = g_cst[bk];
    __syncthreads();

    const uint4* afh = g_afhi + ((size_t)b * SUBT) * 5 * 32 + lid;
    const uint4* afl = g_aflo + ((size_t)b * SUBT) * 5 * 32 + lid;

    for (int ms = wid; ms < SUBT; ms += 8) {
        // load A fragments (coalesced LDG.128, L2-resident)
        uint4 AH[5], AL[5];
        const uint4* ah = afh + (size_t)ms * 5 * 32;
        const uint4* al = afl + (size_t)ms * 5 * 32;
        #pragma unroll
        for (int kc = 0; kc < 5; kc++) {
            AH[kc] = ah[kc * 32];
            AL[kc] = al[kc * 32];
        }

        float qa = 0.f, qb = 0.f;
        #pragma unroll
        for (int jp = 0; jp < 5; jp++) {
            float d0[4] = {0.f, 0.f, 0.f, 0.f};
            float d1[4] = {0.f, 0.f, 0.f, 0.f};
            int n0 = jp * 16 + g;
            int n1 = n0 + 8;
            #pragma unroll
            for (int kc = 0; kc <= jp; kc++) {     // triangular: kc <= j/2
                int row = (kc * 4 + t) * WQ_STRIDE;
                uint2 bh0 = WQ[row + n0];
                uint2 bh1 = WQ[row + n1];
                uint2 bl0 = WQ[20 * WQ_STRIDE + row + n0];
                uint2 bl1 = WQ[20 * WQ_STRIDE + row + n1];
                const uint32_t* ah32 = (const uint32_t*)&AH[kc];
                const uint32_t* al32 = (const uint32_t*)&AL[kc];
                mma16816(d0, ah32, bh0.x, bh0.y);
                mma16816(d1, ah32, bh1.x, bh1.y);
                mma16816(d0, al32, bh0.x, bh0.y);
                mma16816(d1, al32, bh1.x, bh1.y);
                mma16816(d0, ah32, bl0.x, bl0.y);
                mma16816(d1, ah32, bl1.x, bl1.y);
            }
            float2 c0 = cc[2 * jp], c1 = cc[2 * jp + 1];
            float e;
            e = d0[0] - c0.x; qa = fmaf(e, e, qa);
            e = d0[1] - c0.y; qa = fmaf(e, e, qa);
            e = d0[2] - c0.x; qb = fmaf(e, e, qb);
            e = d0[3] - c0.y; qb = fmaf(e, e, qb);
            e = d1[0] - c1.x; qa = fmaf(e, e, qa);
            e = d1[1] - c1.y; qa = fmaf(e, e, qa);
            e = d1[2] - c1.x; qb = fmaf(e, e, qb);
            e = d1[3] - c1.y; qb = fmaf(e, e, qb);
        }
        qa += __shfl_xor_sync(0xffffffffu, qa, 1);
        qa += __shfl_xor_sync(0xffffffffu, qa, 2);
        qb += __shfl_xor_sync(0xffffffffu, qb, 1);
        qb += __shfl_xor_sync(0xffffffffu, qb, 2);
        if (t == 0) {
            int sa = ms * 16 + g, sb = sa + 8;
            if (sa < S_DIM)
                out[((size_t)b * S_DIM + sa) * K_DIM + k] = fmaf(-0.5f, qa, cst);
            if (sb < S_DIM)
                out[((size_t)b * S_DIM + sb) * K_DIM + k] = fmaf(-0.5f, qb, cst);
        }
    }
}

// ---------------------------------------------------------------------------
// Launch order (prep, convert, ll): prep and convert are independent; putting
// prep FIRST makes the ncu positional capture (-s 5 -c 1) land on prep_kernel
// so the prep-vs-ll time split finally becomes visible.
// ---------------------------------------------------------------------------
extern "C" void kernel_launch(void* const* d_in, const int* in_sizes, int n_in,
                              void* d_out, int out_size) {
    const float* x     = (const float*)d_in[0];
    const float* mu    = (const float*)d_in[1];
    const float* sigma = (const float*)d_in[2];
    float* out = (float*)d_out;

    prep_kernel<<<B_DIM * K_DIM, 128>>>(mu, sigma);
    convert_x<<<(B_DIM * SUBT * 5 * 32 + 255) / 256, 256>>>(x);
    ll_mma_kernel<<<dim3(K_DIM, B_DIM), 256>>>(out);
}

// round 15
// speedup vs baseline: 1.5185x; 1.3678x over previous
#include <cuda_runtime.h>
#include <cuda_bf16.h>
#include <math.h>
#include <stdint.h>

#define B_DIM 64
#define S_DIM 1000
#define K_DIM 12
#define N_DIM 80
#define NP 81
#define EPS 1e-5f
#define LOG_2PI 1.8378770664093453f
#define SUBT 63                       // ceil(1000/16) m-subtiles

// ---- device scratch (no allocations allowed) ----
__device__ float g_cst[B_DIM * K_DIM];
__device__ float g_c[B_DIM * K_DIM * N_DIM];
// B operand packed as m16n8k16 B-fragment image:
// idx = bk*1600 + ((kc*4+t)*80 + n);  .x = pack(W[kc*16+2t][n], W[kc*16+2t+1][n])
//                                     .y = pack(W[kc*16+2t+8][n], W[kc*16+2t+9][n])
__device__ uint2 g_wqhi[B_DIM * K_DIM * 1600];
__device__ uint2 g_wqlo[B_DIM * K_DIM * 1600];
// A operand packed as m16n8k16 A-fragment image (uint4 = 4 frag regs per lane/kc):
// idx = ((b*SUBT + ms)*5 + kc)*32 + lane
__device__ uint4 g_afhi[B_DIM * SUBT * 5 * 32];
__device__ uint4 g_aflo[B_DIM * SUBT * 5 * 32];

__device__ __forceinline__ uint32_t pack_bf16(__nv_bfloat16 lo, __nv_bfloat16 hi) {
    return (uint32_t)__bfloat16_as_ushort(lo) | ((uint32_t)__bfloat16_as_ushort(hi) << 16);
}
__device__ __forceinline__ uint32_t hi_pack(float a, float b) {
    return pack_bf16(__float2bfloat16(a), __float2bfloat16(b));
}
__device__ __forceinline__ uint32_t lo_pack(float a, float b) {
    __nv_bfloat16 ha = __float2bfloat16(a), hb = __float2bfloat16(b);
    return pack_bf16(__float2bfloat16(a - __bfloat162float(ha)),
                     __float2bfloat16(b - __bfloat162float(hb)));
}

__device__ __forceinline__ void mma16816(float d[4], const uint32_t a[4], uint32_t b0, uint32_t b1) {
    asm volatile(
        "mma.sync.aligned.m16n8k16.row.col.f32.bf16.bf16.f32 "
        "{%0,%1,%2,%3}, {%4,%5,%6,%7}, {%8,%9}, {%0,%1,%2,%3};"
        : "+f"(d[0]), "+f"(d[1]), "+f"(d[2]), "+f"(d[3])
        : "r"(a[0]), "r"(a[1]), "r"(a[2]), "r"(a[3]), "r"(b0), "r"(b1));
}

// ---------------------------------------------------------------------------
// convert_x: build the A-fragment image. One thread per (b, ms, kc, lane).
// ---------------------------------------------------------------------------
__global__ void __launch_bounds__(256) convert_x(const float* __restrict__ x) {
    int idx = blockIdx.x * 256 + threadIdx.x;
    if (idx >= B_DIM * SUBT * 5 * 32) return;
    int lane = idx & 31;
    int rest = idx >> 5;
    int kc = rest % 5;  rest /= 5;
    int ms = rest % SUBT;
    int b  = rest / SUBT;
    int g = lane >> 2, t = lane & 3;
    int sa = ms * 16 + g, sb = sa + 8;
    int w0 = kc * 8 + t, w1 = w0 + 4;
    const float2* xb = (const float2*)(x + (size_t)b * S_DIM * N_DIM);
    float2 z = make_float2(0.f, 0.f);
    float2 a0 = (sa < S_DIM) ? xb[sa * 40 + w0] : z;
    float2 b0 = (sb < S_DIM) ? xb[sb * 40 + w0] : z;
    float2 a1 = (sa < S_DIM) ? xb[sa * 40 + w1] : z;
    float2 b1 = (sb < S_DIM) ? xb[sb * 40 + w1] : z;
    g_afhi[idx] = make_uint4(hi_pack(a0.x, a0.y), hi_pack(b0.x, b0.y),
                             hi_pack(a1.x, a1.y), hi_pack(b1.x, b1.y));
    g_aflo[idx] = make_uint4(lo_pack(a0.x, a0.y), lo_pack(b0.x, b0.y),
                             lo_pack(a1.x, a1.y), lo_pack(b1.x, b1.y));
}

// ---------------------------------------------------------------------------
// Prep per (b,k), 128 threads. BLOCKED Cholesky (panel 16):
//   - 16x16 diagonal panel factored by warp 0 (__syncwarp pivots)
//   - TRSM of rows below: thread-per-row, register-resident, no syncs
//   - rank-16 trailing update: element-parallel, 2 threads per row
// ~3x fewer warp-instructions and 158 -> ~16 barriers vs rank-1 LDL.
// Downstream (inversion, Tb/M10, c, emission) unchanged from R14.
// ---------------------------------------------------------------------------
__global__ void __launch_bounds__(128) prep_kernel(const float* __restrict__ mu,
                                                   const float* __restrict__ sigma) {
    __shared__ float A[N_DIM * NP];     // 25.9 KB
    __shared__ float Tb[40 * 41];       // 6.6 KB
    __shared__ float rs[N_DIM];
    __shared__ float lg[N_DIM];

    int bk = blockIdx.x;
    int tid = threadIdx.x;
    int wid = tid >> 5, lane = tid & 31;

    const float* sig = sigma + (size_t)bk * N_DIM * N_DIM;
    for (int p = tid; p < N_DIM * N_DIM; p += 128) {
        int i = p / N_DIM, j = p % N_DIM;
        float v = sig[p];
        if (i == j) v += EPS;
        A[i * NP + j] = v;
    }
    __syncthreads();

    // ---- blocked Cholesky, panel = 16
    for (int pp = 0; pp < 5; pp++) {
        int b0 = pp * 16;

        // 1) diagonal 16x16 panel: warp 0 only
        if (wid == 0) {
            for (int jj = 0; jj < 16; jj++) {
                int gj = b0 + jj;
                float d = A[gj * NP + gj];          // broadcast load (pre-sqrt)
                float rsj = rsqrtf(d);
                if (lane == 0) {
                    rs[gj] = rsj;
                    lg[gj] = 0.5f * logf(d);
                    A[gj * NP + gj] = d * rsj;      // sqrt(d)
                }
                int gi = gj + 1 + lane;
                float lv = 0.f;
                bool act = (gi <= b0 + 15);
                if (act) {
                    lv = A[gi * NP + gj] * rsj;     // normalized L column
                    A[gi * NP + gj] = lv;
                }
                __syncwarp();
                if (act) {
                    for (int gt = gj + 1; gt <= gi; gt++)
                        A[gi * NP + gt] -= lv * A[gt * NP + gj];
                }
                __syncwarp();
            }
        }
        __syncthreads();
        if (b0 + 16 >= N_DIM) break;               // last panel: no trailing

        // 2) TRSM: rows below panel, one thread per row, register-resident
        {
            int r = b0 + 16 + tid;
            if (r < N_DIM) {
                float xv[16];
                #pragma unroll
                for (int jj = 0; jj < 16; jj++) xv[jj] = A[r * NP + b0 + jj];
                #pragma unroll
                for (int jj = 0; jj < 16; jj++) {
                    float s = xv[jj];
                    #pragma unroll
                    for (int t = 0; t < jj; t++)
                        s -= xv[t] * A[(b0 + jj) * NP + b0 + t];
                    xv[jj] = s * rs[b0 + jj];
                }
                #pragma unroll
                for (int jj = 0; jj < 16; jj++) A[r * NP + b0 + jj] = xv[jj];
            }
        }
        __syncthreads();

        // 3) rank-16 trailing update (lower triangle only), 2 threads/row
        {
            int r = b0 + 16 + (tid & 63);
            int half = tid >> 6;
            if (r < N_DIM) {
                float Lr[16];
                #pragma unroll
                for (int t = 0; t < 16; t++) Lr[t] = A[r * NP + b0 + t];
                for (int c = b0 + 16 + half; c <= r; c += 2) {
                    float acc = A[r * NP + c];
                    #pragma unroll
                    for (int t = 0; t < 16; t++)
                        acc -= Lr[t] * A[c * NP + b0 + t];
                    A[r * NP + c] = acc;
                }
            }
        }
        __syncthreads();
    }
    __syncthreads();

    // ---- logdet (warp reduce over lg)
    if (tid < 32) {
        float s = lg[tid] + lg[tid + 32] + ((tid + 64 < N_DIM) ? lg[tid + 64] : 0.f);
        #pragma unroll
        for (int o = 16; o > 0; o >>= 1) s += __shfl_xor_sync(0xffffffffu, s, o);
        if (tid == 0) g_cst[bk] = -s - 0.5f * N_DIM * LOG_2PI;
    }
    __syncthreads();

    // ---- two independent 40x40 triangular inversions (one column per thread)
    // M[i][j] (i>j) stored at A[j*NP+i]; diag M = rs
    if (tid < N_DIM) {
        int j = tid;
        int hi = (j < 40) ? 40 : 80;
        for (int i = j + 1; i < hi; i++) {
            float s = A[i * NP + j] * rs[j];
            for (int t = j + 1; t < i; t++)
                s += A[i * NP + t] * A[j * NP + t];
            A[j * NP + i] = -s * rs[i];
        }
    }
    __syncthreads();

    // ---- Tb = L10 * M00
    for (int p = tid; p < 1600; p += 128) {
        int ii = p / 40, jj = p % 40;
        float s = A[(40 + ii) * NP + jj] * rs[jj];
        for (int t = jj + 1; t < 40; t++)
            s += A[(40 + ii) * NP + t] * A[jj * NP + t];
        Tb[ii * 41 + jj] = s;
    }
    __syncthreads();

    // ---- M10 = -M11 * Tb
    for (int p = tid; p < 1600; p += 128) {
        int ii = p / 40, jj = p % 40;
        float s = rs[40 + ii] * Tb[ii * 41 + jj];
        for (int t = 0; t < ii; t++)
            s += A[(40 + t) * NP + (40 + ii)] * Tb[t * 41 + jj];
        A[jj * NP + (40 + ii)] = -s;
    }
    __syncthreads();

    // ---- c = M * mu
    const float* mub = mu + (size_t)bk * N_DIM;
    if (tid < N_DIM) {
        int j = tid;
        float c = mub[j] * rs[j];
        for (int i = 0; i < j; i++) c += mub[i] * A[i * NP + j];
        g_c[bk * N_DIM + j] = c;
    }
    __syncthreads();

    // ---- Emit packed B fragments. W[k][n]: k<n -> A[k*NP+n]; k==n -> rs[k]; else 0
    uint2* wh = g_wqhi + (size_t)bk * 1600;
    uint2* wl = g_wqlo + (size_t)bk * 1600;
    for (int p = tid; p < 1600; p += 128) {
        int kc = p / 320;
        int t  = (p / 80) % 4;
        int n  = p % 80;
        int k0 = kc * 16 + 2 * t;
        float w[4];
        #pragma unroll
        for (int q = 0; q < 4; q++) {
            int k = k0 + ((q >= 2) ? 8 : 0) + (q & 1);
            float v = 0.f;
            if (k < n)       v = A[k * NP + n];
            else if (k == n) v = rs[k];
            w[q] = v;
        }
        wh[p] = make_uint2(hi_pack(w[0], w[1]), hi_pack(w[2], w[3]));
        wl[p] = make_uint2(lo_pack(w[0], w[1]), lo_pack(w[2], w[3]));
    }
}

// ---------------------------------------------------------------------------
// Main (R12 version — best known): CTA per (b,k), 256 threads (8 warps).
// B-fragment image staged ONCE; c/cst in registers; ONE __syncthreads.
// Warps sweep 63 m-subtiles stride-8. Triangular skip: kc <= jp.
// ---------------------------------------------------------------------------
#define WQ_STRIDE 84

__global__ void __launch_bounds__(256) ll_mma_kernel(float* __restrict__ out) {
    __shared__ uint2 WQ[2 * 20 * WQ_STRIDE];   // 26880 B

    int tid = threadIdx.x;
    int wid = tid >> 5, lid = tid & 31;
    int g = lid >> 2, t = lid & 3;
    int k = blockIdx.x, b = blockIdx.y;
    int bk = b * K_DIM + k;

    // stage B fragments (once)
    {
        const uint2* wh = g_wqhi + (size_t)bk * 1600;
        const uint2* wl = g_wqlo + (size_t)bk * 1600;
        for (int p = tid; p < 1600; p += 256) {
            int row = p / 80, n = p % 80;
            WQ[row * WQ_STRIDE + n]                  = wh[p];
            WQ[20 * WQ_STRIDE + row * WQ_STRIDE + n] = wl[p];
        }
    }
    // c fragments + cst to registers
    float2 cc[10];
    {
        const float* cbase = g_c + bk * N_DIM;
        #pragma unroll
        for (int j = 0; j < 10; j++)
            cc[j] = *(const float2*)(cbase + j * 8 + 2 * t);
    }
    float cst = g_cst[bk];
    __syncthreads();

    const uint4* afh = g_afhi + ((size_t)b * SUBT) * 5 * 32 + lid;
    const uint4* afl = g_aflo + ((size_t)b * SUBT) * 5 * 32 + lid;

    for (int ms = wid; ms < SUBT; ms += 8) {
        // load A fragments (coalesced LDG.128, L2-resident)
        uint4 AH[5], AL[5];
        const uint4* ah = afh + (size_t)ms * 5 * 32;
        const uint4* al = afl + (size_t)ms * 5 * 32;
        #pragma unroll
        for (int kc = 0; kc < 5; kc++) {
            AH[kc] = ah[kc * 32];
            AL[kc] = al[kc * 32];
        }

        float qa = 0.f, qb = 0.f;
        #pragma unroll
        for (int jp = 0; jp < 5; jp++) {
            float d0[4] = {0.f, 0.f, 0.f, 0.f};
            float d1[4] = {0.f, 0.f, 0.f, 0.f};
            int n0 = jp * 16 + g;
            int n1 = n0 + 8;
            #pragma unroll
            for (int kc = 0; kc <= jp; kc++) {     // triangular: kc <= j/2
                int row = (kc * 4 + t) * WQ_STRIDE;
                uint2 bh0 = WQ[row + n0];
                uint2 bh1 = WQ[row + n1];
                uint2 bl0 = WQ[20 * WQ_STRIDE + row + n0];
                uint2 bl1 = WQ[20 * WQ_STRIDE + row + n1];
                const uint32_t* ah32 = (const uint32_t*)&AH[kc];
                const uint32_t* al32 = (const uint32_t*)&AL[kc];
                mma16816(d0, ah32, bh0.x, bh0.y);
                mma16816(d1, ah32, bh1.x, bh1.y);
                mma16816(d0, al32, bh0.x, bh0.y);
                mma16816(d1, al32, bh1.x, bh1.y);
                mma16816(d0, ah32, bl0.x, bl0.y);
                mma16816(d1, ah32, bl1.x, bl1.y);
            }
            float2 c0 = cc[2 * jp], c1 = cc[2 * jp + 1];
            float e;
            e = d0[0] - c0.x; qa = fmaf(e, e, qa);
            e = d0[1] - c0.y; qa = fmaf(e, e, qa);
            e = d0[2] - c0.x; qb = fmaf(e, e, qb);
            e = d0[3] - c0.y; qb = fmaf(e, e, qb);
            e = d1[0] - c1.x; qa = fmaf(e, e, qa);
            e = d1[1] - c1.y; qa = fmaf(e, e, qa);
            e = d1[2] - c1.x; qb = fmaf(e, e, qb);
            e = d1[3] - c1.y; qb = fmaf(e, e, qb);
        }
        qa += __shfl_xor_sync(0xffffffffu, qa, 1);
        qa += __shfl_xor_sync(0xffffffffu, qa, 2);
        qb += __shfl_xor_sync(0xffffffffu, qb, 1);
        qb += __shfl_xor_sync(0xffffffffu, qb, 2);
        if (t == 0) {
            int sa = ms * 16 + g, sb = sa + 8;
            if (sa < S_DIM)
                out[((size_t)b * S_DIM + sa) * K_DIM + k] = fmaf(-0.5f, qa, cst);
            if (sb < S_DIM)
                out[((size_t)b * S_DIM + sb) * K_DIM + k] = fmaf(-0.5f, qb, cst);
        }
    }
}

// ---------------------------------------------------------------------------
extern "C" void kernel_launch(void* const* d_in, const int* in_sizes, int n_in,
                              void* d_out, int out_size) {
    const float* x     = (const float*)d_in[0];
    const float* mu    = (const float*)d_in[1];
    const float* sigma = (const float*)d_in[2];
    float* out = (float*)d_out;

    prep_kernel<<<B_DIM * K_DIM, 128>>>(mu, sigma);
    convert_x<<<(B_DIM * SUBT * 5 * 32 + 255) / 256, 256>>>(x);
    ll_mma_kernel<<<dim3(K_DIM, B_DIM), 256>>>(out);
}